// round 4
// baseline (speedup 1.0000x reference)
#include <cuda_runtime.h>
#include <cuda_bf16.h>
#include <cstdint>

#define BQ    4
#define NSEQ  200000
#define EDIM  128
#define NIDX  2048
#define ROWS  (BQ * NSEQ)            /* 800000 */
#define NTILES (ROWS / 128)          /* 6250 exact */
#define OUT_ELEMS (BQ * NIDX * EDIM) /* 1048576 */
#define ATTN_OFF  OUT_ELEMS
#define NSEG (BQ * NIDX)             /* 8192 */

// ---------------- device scratch (no cudaMalloc allowed) ----------------
__device__ float    g_imp[ROWS];       // importance, then exp(imp - m)
__device__ unsigned g_segmax_u[NSEG];  // monotonic-encoded float max
__device__ float    g_segsum[NSEG];

// ---------------- helpers ----------------
__device__ __forceinline__ uint32_t smem_u32(const void* p) {
    uint32_t a;
    asm("{ .reg .u64 t; cvta.to.shared.u64 t, %1; cvt.u32.u64 %0, t; }" : "=r"(a) : "l"(p));
    return a;
}

#define LDSM_X4(r0, r1, r2, r3, addr) \
    asm volatile("ldmatrix.sync.aligned.m8n8.x4.shared.b16 {%0,%1,%2,%3}, [%4];" \
        : "=r"(r0), "=r"(r1), "=r"(r2), "=r"(r3) : "r"(addr))

#define MMA16816(d, a0, a1, a2, a3, b0, b1) \
    asm volatile("mma.sync.aligned.m16n8k16.row.col.f32.bf16.bf16.f32 " \
        "{%0,%1,%2,%3}, {%4,%5,%6,%7}, {%8,%9}, {%0,%1,%2,%3};" \
        : "+f"((d)[0]), "+f"((d)[1]), "+f"((d)[2]), "+f"((d)[3]) \
        : "r"(a0), "r"(a1), "r"(a2), "r"(a3), "r"(b0), "r"(b1))

// monotonic float<->uint for atomicMax
__device__ __forceinline__ unsigned fenc(float f) {
    unsigned u = __float_as_uint(f);
    return u ^ ((unsigned)((int)u >> 31) | 0x80000000u);
}
__device__ __forceinline__ float fdec(unsigned u) {
    unsigned v = (u & 0x80000000u) ? (u ^ 0x80000000u) : ~u;
    return __uint_as_float(v);
}

// ---------------- SMEM layout (K1) ----------------
// tiles: 128 rows x 136 bf16 (128 data + 8 pad) -> 272 B row stride, conflict-free ldmatrix
#define ROW_B     272
#define TILE_PB   (128 * ROW_B)      /* 34816 */
#define SM_B      0                  /* 512B bias   */
#define SM_CTX    512                /* 512B ctx    */
#define SM_PACC   1024               /* 128*2 f32 = 1024B */
#define SM_TILES  2048
#define SM_XHI    (SM_TILES + 0 * TILE_PB)
#define SM_XLO    (SM_TILES + 1 * TILE_PB)
#define SM_WHI    (SM_TILES + 2 * TILE_PB)
#define SM_WLO    (SM_TILES + 3 * TILE_PB)
#define SMEM_TOTAL (SM_TILES + 4 * TILE_PB)   /* 141312 */

// store 4 consecutive f32 as hi/lo bf16 pairs into two padded tiles
__device__ __forceinline__ void store_hilo(char* smem, int hi_base, int lo_base,
                                           int row, int col, float4 v) {
    __nv_bfloat16 h0 = __float2bfloat16(v.x), h1 = __float2bfloat16(v.y);
    __nv_bfloat16 h2 = __float2bfloat16(v.z), h3 = __float2bfloat16(v.w);
    __nv_bfloat16 l0 = __float2bfloat16(v.x - __bfloat162float(h0));
    __nv_bfloat16 l1 = __float2bfloat16(v.y - __bfloat162float(h1));
    __nv_bfloat16 l2 = __float2bfloat16(v.z - __bfloat162float(h2));
    __nv_bfloat16 l3 = __float2bfloat16(v.w - __bfloat162float(h3));
    uint32_t off = (uint32_t)(row * ROW_B + col * 2);
    __nv_bfloat162 hA; hA.x = h0; hA.y = h1;
    __nv_bfloat162 hB; hB.x = h2; hB.y = h3;
    __nv_bfloat162 lA; lA.x = l0; lA.y = l1;
    __nv_bfloat162 lB; lB.x = l2; lB.y = l3;
    uint2 hu, lu;
    hu.x = *(uint32_t*)&hA; hu.y = *(uint32_t*)&hB;
    lu.x = *(uint32_t*)&lA; lu.y = *(uint32_t*)&lB;
    *(uint2*)(smem + hi_base + off) = hu;
    *(uint2*)(smem + lo_base + off) = lu;
}

// =========================== K0: init ===========================
__global__ void k0_init(float* out) {
    int i = blockIdx.x * blockDim.x + threadIdx.x;
    if (i < OUT_ELEMS) out[i] = 0.0f;
    if (i < NSEG) { g_segmax_u[i] = 0u; g_segsum[i] = 0.0f; }
}

// ============ K1: GEMM + tanh + importance + segment max ============
__global__ __launch_bounds__(256, 1)
void k1_importance(const float* __restrict__ x, const float* __restrict__ W,
                   const float* __restrict__ bv, const float* __restrict__ ctx,
                   const int* __restrict__ mask, const int* __restrict__ index) {
    extern __shared__ char smem[];
    uint32_t sbase = smem_u32(smem);
    int tid = threadIdx.x;
    int l = tid & 31, wid = tid >> 5;
    int warp_r = wid & 3;       // row group: rows 32*warp_r .. +31
    int warp_c = wid >> 2;      // col group: cols 64*warp_c .. +63
    int tile = blockIdx.x;

    if (tid < 128) {
        ((float*)(smem + SM_B))[tid]   = bv[tid];
        ((float*)(smem + SM_CTX))[tid] = ctx[tid];
    }

    // load + split: x tile (this CTA's 128 rows) and W (128x128)
    const float4* x4 = (const float4*)(x + (size_t)tile * 128 * 128);
    const float4* w4 = (const float4*)W;
#pragma unroll 4
    for (int i = 0; i < 16; i++) {
        int idx4 = i * 256 + tid;              // 0..4095 float4s
        int row = idx4 >> 5, col = (idx4 & 31) * 4;
        store_hilo(smem, SM_XHI, SM_XLO, row, col, __ldg(&x4[idx4]));
        store_hilo(smem, SM_WHI, SM_WLO, row, col, __ldg(&w4[idx4]));
    }
    __syncthreads();

    // ---- per-lane ldmatrix base offsets (bytes within a tile) ----
    // A (x): lanes 0-15 rows (l&15), lanes>=16 add k+8 halves
    uint32_t a_off = (uint32_t)((32 * warp_r + (l & 15)) * ROW_B + ((l >> 4) << 3) * 2);
    // B (W): x4 covers an n-pair (16 n-rows): n = (l&7) + ((l>>4)<<3), k-half = ((l>>3)&1)*8
    uint32_t b_off = (uint32_t)((64 * warp_c + (l & 7) + ((l >> 4) << 3)) * ROW_B
                                + (((l >> 3) & 1) << 3) * 2);

    float d[2][8][4];
#pragma unroll
    for (int mb = 0; mb < 2; mb++)
#pragma unroll
        for (int nb = 0; nb < 8; nb++)
#pragma unroll
            for (int r = 0; r < 4; r++) d[mb][nb][r] = 0.0f;

    // 3 passes: Xhi*Whi, Xhi*Wlo, Xlo*Whi
#pragma unroll
    for (int pass = 0; pass < 3; pass++) {
        uint32_t abase = sbase + (pass == 2 ? SM_XLO : SM_XHI) + a_off;
        uint32_t bbase = sbase + (pass == 1 ? SM_WLO : SM_WHI) + b_off;
#pragma unroll
        for (int k = 0; k < 8; k++) {
            uint32_t ka = abase + k * 32;      // k16 step = 32B along row
            uint32_t kb = bbase + k * 32;
            uint32_t a0[4], a1[4];
            LDSM_X4(a0[0], a0[1], a0[2], a0[3], ka);
            LDSM_X4(a1[0], a1[1], a1[2], a1[3], ka + 16 * ROW_B);
            uint32_t b[4][4];
#pragma unroll
            for (int p = 0; p < 4; p++)
                LDSM_X4(b[p][0], b[p][1], b[p][2], b[p][3], kb + p * 16 * ROW_B);
#pragma unroll
            for (int nb = 0; nb < 8; nb++) {
                uint32_t bb0 = b[nb >> 1][(nb & 1) ? 2 : 0];
                uint32_t bb1 = b[nb >> 1][(nb & 1) ? 3 : 1];
                MMA16816(d[0][nb], a0[0], a0[1], a0[2], a0[3], bb0, bb1);
                MMA16816(d[1][nb], a1[0], a1[1], a1[2], a1[3], bb0, bb1);
            }
        }
    }

    // ---- epilogue: tanh + ctx-dot directly on fragments ----
    // frag element map: reg0:(r,c) reg1:(r,c+1) reg2:(r+8,c) reg3:(r+8,c+1),
    // r = l>>2, c = (l&3)*2
    const float* sb = (const float*)(smem + SM_B);
    const float* sc = (const float*)(smem + SM_CTX);
    float acc[4] = {0.f, 0.f, 0.f, 0.f};     // [mb*2 + hi8]
#pragma unroll
    for (int mb = 0; mb < 2; mb++) {
#pragma unroll
        for (int nb = 0; nb < 8; nb++) {
            int c0 = 64 * warp_c + nb * 8 + (l & 3) * 2;
#pragma unroll
            for (int r = 0; r < 4; r++) {
                int c = c0 + (r & 1);
                float pre = d[mb][nb][r] + sb[c];
                float t = __expf(2.0f * pre);                  // tanh(x) = 1 - 2/(e^{2x}+1)
                float th = 1.0f - __fdividef(2.0f, t + 1.0f);  // safe at +-inf
                acc[mb * 2 + (r >> 1)] = fmaf(sc[c], th, acc[mb * 2 + (r >> 1)]);
            }
        }
    }
    // reduce over the 4 lanes of each quad (same rows, different cols)
#pragma unroll
    for (int s = 0; s < 4; s++) {
        acc[s] += __shfl_xor_sync(0xFFFFFFFFu, acc[s], 1);
        acc[s] += __shfl_xor_sync(0xFFFFFFFFu, acc[s], 2);
    }
    float* pacc = (float*)(smem + SM_PACC);
    if ((l & 3) == 0) {
#pragma unroll
        for (int s = 0; s < 4; s++) {
            int row = 32 * warp_r + (s >> 1) * 16 + (s & 1) * 8 + (l >> 2);
            pacc[row * 2 + warp_c] = acc[s];
        }
    }
    __syncthreads();

    if (tid < 128) {
        float impv = (pacc[tid * 2] + pacc[tid * 2 + 1]) * 0.08838834764831843f;
        int row = tile * 128 + tid;
        if (mask[row] == 0) impv = -1e9f;
        g_imp[row] = impv;
        int seg = index[row];
        int bq = row / NSEQ;
        atomicMax(&g_segmax_u[bq * NIDX + seg], fenc(impv));
    }
}

// ============ K2: exp + segment sum ============
__global__ __launch_bounds__(256)
void k2_expsum(const int* __restrict__ index) {
    int row = blockIdx.x * blockDim.x + threadIdx.x;
    if (row >= ROWS) return;
    float impv = g_imp[row];
    int seg = index[row];
    int bq = row / NSEQ;
    float m = fdec(g_segmax_u[bq * NIDX + seg]);
    float e = __expf(impv - m);    // mixed-seg masked rows -> 0; all-masked seg -> 1 each
    g_imp[row] = e;
    atomicAdd(&g_segsum[bq * NIDX + seg], e);
}

// ============ K3: weights + scatter-add of x ============
__global__ __launch_bounds__(256)
void k3_scatter(const float* __restrict__ x, const int* __restrict__ index,
                float* __restrict__ out) {
    int warp_in_blk = threadIdx.x >> 5;
    int lane = threadIdx.x & 31;
    long long row = (long long)blockIdx.x * 8 + warp_in_blk;
    if (row >= ROWS) return;

    float w = 0.0f; int seg = 0, bq = 0;
    if (lane == 0) {
        float e = g_imp[row];
        seg = index[row];
        bq = (int)(row / NSEQ);
        float s = g_segsum[bq * NIDX + seg];
        w = e / s;
        out[ATTN_OFF + row] = w;
    }
    w   = __shfl_sync(0xFFFFFFFFu, w, 0);
    seg = __shfl_sync(0xFFFFFFFFu, seg, 0);
    bq  = __shfl_sync(0xFFFFFFFFu, bq, 0);

    if (w != 0.0f) {
        const float4* x4 = (const float4*)(x) + row * 32 + lane;
        float4 v = __ldg(x4);
        float* dst = out + ((size_t)(bq * NIDX + seg) << 7) + lane * 4;
        asm volatile("red.global.add.v4.f32 [%0], {%1, %2, %3, %4};"
                     :: "l"(dst), "f"(v.x * w), "f"(v.y * w), "f"(v.z * w), "f"(v.w * w)
                     : "memory");
    }
}

// ============================ launch ============================
extern "C" void kernel_launch(void* const* d_in, const int* in_sizes, int n_in,
                              void* d_out, int out_size) {
    const float* x     = (const float*)d_in[0];
    const float* W     = (const float*)d_in[1];
    const float* bv    = (const float*)d_in[2];
    const float* ctx   = (const float*)d_in[3];
    const int*   mask  = (const int*)d_in[4];
    const int*   index = (const int*)d_in[5];
    float* out = (float*)d_out;

    cudaFuncSetAttribute(k1_importance, cudaFuncAttributeMaxDynamicSharedMemorySize, SMEM_TOTAL);

    k0_init<<<(OUT_ELEMS + 255) / 256, 256>>>(out);
    k1_importance<<<NTILES, 256, SMEM_TOTAL>>>(x, W, bv, ctx, mask, index);
    k2_expsum<<<(ROWS + 255) / 256, 256>>>(index);
    k3_scatter<<<(ROWS / 8), 256>>>(x, index, out);
}

// round 5
// speedup vs baseline: 1.7490x; 1.7490x over previous
#include <cuda_runtime.h>
#include <cuda_bf16.h>
#include <cstdint>

#define BQ    4
#define NSEQ  200000
#define EDIM  128
#define NIDX  2048
#define ROWS  (BQ * NSEQ)            /* 800000 */
#define NTILES (ROWS / 128)          /* 6250 exact */
#define OUT_ELEMS (BQ * NIDX * EDIM) /* 1048576 */
#define ATTN_OFF  OUT_ELEMS
#define NSEG (BQ * NIDX)             /* 8192 */

// ---------------- device scratch (no cudaMalloc allowed) ----------------
__device__ float    g_imp[ROWS];        // importance, then exp(imp - m)
__device__ unsigned g_segmax_u[NSEG];   // monotonic-encoded float max
__device__ float    g_segsum[NSEG];
__device__ float    g_Wr[EDIM * EDIM];  // W pre-rounded to tf32 grid (RNA)
__device__ unsigned g_tilectr;          // work-stealing tile counter

// ---------------- helpers ----------------
__device__ __forceinline__ uint32_t smem_u32(const void* p) {
    uint32_t a;
    asm("{ .reg .u64 t; cvta.to.shared.u64 t, %1; cvt.u32.u64 %0, t; }" : "=r"(a) : "l"(p));
    return a;
}
__device__ __forceinline__ uint32_t f2tf32_rna_bits(float f) {
    uint32_t r;
    asm("cvt.rna.tf32.f32 %0, %1;" : "=r"(r) : "f"(f));
    return r;
}
__device__ __forceinline__ void cp_async16(uint32_t dst, const void* src) {
    asm volatile("cp.async.cg.shared.global [%0], [%1], 16;" :: "r"(dst), "l"(src));
}
#define CP_COMMIT()  asm volatile("cp.async.commit_group;" ::: "memory")
#define CP_WAIT(N)   asm volatile("cp.async.wait_group %0;" :: "n"(N) : "memory")

#define MMA_TF32(d, A, B) \
    asm volatile("mma.sync.aligned.m16n8k8.row.col.f32.tf32.tf32.f32 " \
        "{%0,%1,%2,%3}, {%4,%5,%6,%7}, {%8,%9}, {%0,%1,%2,%3};" \
        : "+f"((d)[0]), "+f"((d)[1]), "+f"((d)[2]), "+f"((d)[3]) \
        : "r"((A)[0]), "r"((A)[1]), "r"((A)[2]), "r"((A)[3]), "r"((B)[0]), "r"((B)[1]))

// monotonic float<->uint for atomicMax
__device__ __forceinline__ unsigned fenc(float f) {
    unsigned u = __float_as_uint(f);
    return u ^ ((unsigned)((int)u >> 31) | 0x80000000u);
}
__device__ __forceinline__ float fdec(unsigned u) {
    unsigned v = (u & 0x80000000u) ? (u ^ 0x80000000u) : ~u;
    return __uint_as_float(v);
}

// ---------------- SMEM layout (K1) ----------------
// tiles: 128 rows x 132 f32 (128 data + 4 pad) -> 528 B row stride
// LDS bank check: (row*132 + k) % 32 == (row*4 + k) % 32 == lane  (conflict-free)
#define ROWF      132
#define ROW_B     528
#define TILE_PB   (128 * ROW_B)       /* 67584 */
#define SM_B      0                   /* 512B bias   */
#define SM_CTX    512                 /* 512B ctx    */
#define SM_PACC   1024                /* 1024B       */
#define SM_T      2048                /* 16B tile broadcast */
#define SM_W      2560
#define SM_X0     (SM_W + TILE_PB)    /* 70144  */
#define SM_X1     (SM_X0 + TILE_PB)   /* 137728 */
#define SMEM_TOTAL (SM_X1 + TILE_PB)  /* 205312 */

// async 16B-chunk copy of a 128x128 f32 tile (gmem contiguous) into padded smem
__device__ __forceinline__ void load_tile_async(uint32_t sm_dst, const float* gsrc, int tid) {
#pragma unroll
    for (int i = 0; i < 16; i++) {
        int c = i * 256 + tid;            // 0..4095 16B chunks
        int row = c >> 5, u = c & 31;
        cp_async16(sm_dst + row * ROW_B + u * 16, gsrc + row * 128 + u * 4);
    }
}

// =========================== K0: init ===========================
__global__ void k0_init(float* out, const float* __restrict__ W) {
    int i = blockIdx.x * blockDim.x + threadIdx.x;
    if (i < OUT_ELEMS) out[i] = 0.0f;
    if (i < NSEG) { g_segmax_u[i] = 0u; g_segsum[i] = 0.0f; }
    if (i < EDIM * EDIM) g_Wr[i] = __uint_as_float(f2tf32_rna_bits(W[i]));
    if (i == 0) g_tilectr = 0u;
}

// ============ K1: persistent tf32 GEMM + tanh + importance + segmax ============
__global__ __launch_bounds__(256, 1)
void k1_importance(const float* __restrict__ x,
                   const float* __restrict__ bv, const float* __restrict__ ctx,
                   const int* __restrict__ mask, const int* __restrict__ index) {
    extern __shared__ char smem[];
    uint32_t sbase = smem_u32(smem);
    int tid = threadIdx.x;
    int l = tid & 31, wid = tid >> 5;
    int warp_r = wid & 3;        // rows 32*warp_r .. +31
    int warp_c = wid >> 2;       // cols 64*warp_c .. +63
    int r0 = l >> 2, c0 = l & 3;
    int* smt = (int*)(smem + SM_T);

    if (tid < 128) {
        ((float*)(smem + SM_B))[tid]   = bv[tid];
        ((float*)(smem + SM_CTX))[tid] = ctx[tid];
    }
    if (tid == 0) smt[0] = (int)atomicAdd(&g_tilectr, 1u);
    __syncthreads();
    int t = smt[0];
    if (t >= NTILES) return;     // late CTA under work stealing

    load_tile_async(sbase + SM_W, g_Wr, tid);
    load_tile_async(sbase + SM_X0, x + (size_t)t * 16384, tid);
    CP_COMMIT();

    // per-lane fragment base indices (f32 units)
    const int a_base0 = (32 * warp_r + r0) * ROWF + c0;
    const int b_base0 = (64 * warp_c + r0) * ROWF + c0;
    const float* Wp = (const float*)(smem + SM_W);
    const float* sb = (const float*)(smem + SM_B);
    const float* sc = (const float*)(smem + SM_CTX);
    float* pacc = (float*)(smem + SM_PACC);

    int pp = 0;
    for (;;) {
        if (tid == 0) smt[0] = (int)atomicAdd(&g_tilectr, 1u);
        __syncthreads();                       // also fences prev-iter smem reads
        int tn = smt[0];
        bool pend = (tn < NTILES);
        if (pend) {
            load_tile_async(sbase + SM_X0 + (uint32_t)(pp ^ 1) * TILE_PB,
                            x + (size_t)tn * 16384, tid);
            CP_COMMIT();
            CP_WAIT(1);                        // current tile's group done
        } else {
            CP_WAIT(0);
        }
        __syncthreads();

        const float* Xp = (const float*)(smem + SM_X0 + (uint32_t)pp * TILE_PB);
        float d[2][8][4];
#pragma unroll
        for (int mb = 0; mb < 2; mb++)
#pragma unroll
            for (int nb = 0; nb < 8; nb++)
#pragma unroll
                for (int r = 0; r < 4; r++) d[mb][nb][r] = 0.0f;

#pragma unroll
        for (int kk = 0; kk < 16; kk++) {
            uint32_t A[2][4];
#pragma unroll
            for (int mb = 0; mb < 2; mb++) {
                int ab = a_base0 + kk * 8 + mb * 16 * ROWF;
                A[mb][0] = f2tf32_rna_bits(Xp[ab]);
                A[mb][1] = f2tf32_rna_bits(Xp[ab + 8 * ROWF]);
                A[mb][2] = f2tf32_rna_bits(Xp[ab + 4]);
                A[mb][3] = f2tf32_rna_bits(Xp[ab + 8 * ROWF + 4]);
            }
            uint32_t Bf[8][2];
#pragma unroll
            for (int nb = 0; nb < 8; nb++) {
                int bb = b_base0 + kk * 8 + nb * 8 * ROWF;
                Bf[nb][0] = __float_as_uint(Wp[bb]);       // already tf32-grid (RNA)
                Bf[nb][1] = __float_as_uint(Wp[bb + 4]);
            }
#pragma unroll
            for (int nb = 0; nb < 8; nb++) {
                MMA_TF32(d[0][nb], A[0], Bf[nb]);
                MMA_TF32(d[1][nb], A[1], Bf[nb]);
            }
        }

        // ---- epilogue: tanh + ctx-dot on fragments ----
        float acc[4] = {0.f, 0.f, 0.f, 0.f};   // [mb*2 + hi8]
#pragma unroll
        for (int mb = 0; mb < 2; mb++) {
#pragma unroll
            for (int nb = 0; nb < 8; nb++) {
                int cb = 64 * warp_c + nb * 8 + c0 * 2;
#pragma unroll
                for (int r = 0; r < 4; r++) {
                    int c = cb + (r & 1);
                    float pre = d[mb][nb][r] + sb[c];
                    float tt = __expf(2.0f * pre);                  // tanh = 1 - 2/(e^{2x}+1)
                    float th = 1.0f - __fdividef(2.0f, tt + 1.0f);  // safe at +-inf
                    acc[mb * 2 + (r >> 1)] = fmaf(sc[c], th, acc[mb * 2 + (r >> 1)]);
                }
            }
        }
#pragma unroll
        for (int s = 0; s < 4; s++) {
            acc[s] += __shfl_xor_sync(0xFFFFFFFFu, acc[s], 1);
            acc[s] += __shfl_xor_sync(0xFFFFFFFFu, acc[s], 2);
        }
        if (c0 == 0) {
#pragma unroll
            for (int s = 0; s < 4; s++) {
                int row = 32 * warp_r + 16 * (s >> 1) + 8 * (s & 1) + r0;
                pacc[row * 2 + warp_c] = acc[s];
            }
        }
        __syncthreads();

        if (tid < 128) {
            float impv = (pacc[tid * 2] + pacc[tid * 2 + 1]) * 0.08838834764831843f;
            int row = t * 128 + tid;
            if (mask[row] == 0) impv = -1e9f;
            g_imp[row] = impv;
            int seg = index[row];
            int bq = row / NSEQ;
            atomicMax(&g_segmax_u[bq * NIDX + seg], fenc(impv));
        }

        if (!pend) break;
        t = tn; pp ^= 1;
    }
}

// ============ K2: exp + segment sum ============
__global__ __launch_bounds__(256)
void k2_expsum(const int* __restrict__ index) {
    int row = blockIdx.x * blockDim.x + threadIdx.x;
    if (row >= ROWS) return;
    float impv = g_imp[row];
    int seg = index[row];
    int bq = row / NSEQ;
    float m = fdec(g_segmax_u[bq * NIDX + seg]);
    float e = __expf(impv - m);
    g_imp[row] = e;
    atomicAdd(&g_segsum[bq * NIDX + seg], e);
}

// ============ K3: weights + scatter-add of x (32 rows per warp) ============
__global__ __launch_bounds__(256)
void k3_scatter(const float* __restrict__ x, const int* __restrict__ index,
                float* __restrict__ out) {
    int warp = (blockIdx.x << 3) + (threadIdx.x >> 5);   // 25000 warps
    int lane = threadIdx.x & 31;
    int rbase = warp * 32;                               // NSEQ % 32 == 0: no bq straddle
    int row = rbase + lane;

    float e  = g_imp[row];
    int seg  = index[row];
    int bq   = row / NSEQ;
    int segg = bq * NIDX + seg;
    float s  = g_segsum[segg];
    float w  = e / s;
    out[ATTN_OFF + row] = w;

    unsigned act = __ballot_sync(0xFFFFFFFFu, w != 0.0f);
    while (act) {
        int i = __ffs(act) - 1;
        act &= (act - 1);
        float wi = __shfl_sync(0xFFFFFFFFu, w, i);
        int si   = __shfl_sync(0xFFFFFFFFu, segg, i);
        size_t ri = (size_t)(rbase + i);
        float4 v = __ldg((const float4*)x + ri * 32 + lane);
        float* dst = out + ((size_t)si << 7) + lane * 4;
        asm volatile("red.global.add.v4.f32 [%0], {%1, %2, %3, %4};"
                     :: "l"(dst), "f"(v.x * wi), "f"(v.y * wi), "f"(v.z * wi), "f"(v.w * wi)
                     : "memory");
    }
}

// ============================ launch ============================
extern "C" void kernel_launch(void* const* d_in, const int* in_sizes, int n_in,
                              void* d_out, int out_size) {
    const float* x     = (const float*)d_in[0];
    const float* W     = (const float*)d_in[1];
    const float* bv    = (const float*)d_in[2];
    const float* ctx   = (const float*)d_in[3];
    const int*   mask  = (const int*)d_in[4];
    const int*   index = (const int*)d_in[5];
    float* out = (float*)d_out;

    cudaFuncSetAttribute(k1_importance, cudaFuncAttributeMaxDynamicSharedMemorySize, SMEM_TOTAL);

    k0_init<<<(OUT_ELEMS + 255) / 256, 256>>>(out, W);
    k1_importance<<<152, 256, SMEM_TOTAL>>>(x, bv, ctx, mask, index);
    k2_expsum<<<(ROWS + 255) / 256, 256>>>(index);
    k3_scatter<<<(ROWS / 256), 256>>>(x, index, out);
}

// round 6
// speedup vs baseline: 2.1644x; 1.2375x over previous
#include <cuda_runtime.h>
#include <cuda_fp16.h>
#include <cstdint>

#define BQ    4
#define NSEQ  200000
#define EDIM  128
#define NIDX  2048
#define ROWS  (BQ * NSEQ)            /* 800000 */
#define NTILES (ROWS / 128)          /* 6250 exact */
#define OUT_ELEMS (BQ * NIDX * EDIM) /* 1048576 */
#define ATTN_OFF  OUT_ELEMS
#define NSEG (BQ * NIDX)             /* 8192 */

// ---------------- device scratch (no cudaMalloc allowed) ----------------
__device__ float    g_imp[ROWS];        // importance, then exp(imp - m)
__device__ unsigned g_segmax_u[NSEG];   // monotonic-encoded float max
__device__ float    g_segsum[NSEG];
__device__ uint32_t g_Wfrag[8192];      // W as fragment-ordered fp16x2 pairs (32 KB)
__device__ unsigned g_tilectr;          // work-stealing tile counter

// ---------------- helpers ----------------
__device__ __forceinline__ uint32_t smem_u32(const void* p) {
    uint32_t a;
    asm("{ .reg .u64 t; cvta.to.shared.u64 t, %1; cvt.u32.u64 %0, t; }" : "=r"(a) : "l"(p));
    return a;
}
// pack two f32 -> f16x2 (lo = first arg)
__device__ __forceinline__ uint32_t f16x2_pack(float lo, float hi) {
    uint32_t r;
    asm("cvt.rn.f16x2.f32 %0, %1, %2;" : "=r"(r) : "f"(hi), "f"(lo));
    return r;
}
__device__ __forceinline__ void cp_async16(uint32_t dst, const void* src) {
    asm volatile("cp.async.cg.shared.global [%0], [%1], 16;" :: "r"(dst), "l"(src));
}
#define CP_COMMIT()  asm volatile("cp.async.commit_group;" ::: "memory")
#define CP_WAIT(N)   asm volatile("cp.async.wait_group %0;" :: "n"(N) : "memory")

#define LDS128(r0_, r1_, r2_, r3_, addr) \
    asm volatile("ld.shared.v4.u32 {%0,%1,%2,%3}, [%4];" \
        : "=r"(r0_), "=r"(r1_), "=r"(r2_), "=r"(r3_) : "r"(addr))

#define MMA_F16(d, a0, a1, a2, a3, b0, b1) \
    asm volatile("mma.sync.aligned.m16n8k16.row.col.f32.f16.f16.f32 " \
        "{%0,%1,%2,%3}, {%4,%5,%6,%7}, {%8,%9}, {%0,%1,%2,%3};" \
        : "+f"((d)[0]), "+f"((d)[1]), "+f"((d)[2]), "+f"((d)[3]) \
        : "r"(a0), "r"(a1), "r"(a2), "r"(a3), "r"(b0), "r"(b1))

// monotonic float<->uint for atomicMax
__device__ __forceinline__ unsigned fenc(float f) {
    unsigned u = __float_as_uint(f);
    return u ^ ((unsigned)((int)u >> 31) | 0x80000000u);
}
__device__ __forceinline__ float fdec(unsigned u) {
    unsigned v = (u & 0x80000000u) ? (u ^ 0x80000000u) : ~u;
    return __uint_as_float(v);
}

// ---------------- SMEM layout (K1) ----------------
// X tiles: 128 rows x 136 f32 (128 data + 8 pad) -> 544 B row stride.
//   A-pair LDS.64 bank = (8*r0 + 2*c0) % 32 -> 16 lanes cover all 32 banks: conflict-free.
// W frags: [wc(2)][step(8)][lane(32)] x 64B payload, padded to 80 B/lane stride.
//   LDS.128 phase (8 lanes): start banks (l*20)%32 = {0,20,8,28,16,4,24,12}: conflict-free.
#define ROWF      136
#define ROW_B     544
#define TILE_PB   (128 * ROW_B)       /* 69632 */
#define SM_B      0                   /* 512B bias   */
#define SM_CTX    512                 /* 512B ctx    */
#define SM_PACC   1024                /* 1024B       */
#define SM_T      2048                /* 16B tile broadcast */
#define SM_WF     2176                /* 40960B W fragments */
#define SM_X0     (SM_WF + 40960)     /* 43136  */
#define SM_X1     (SM_X0 + TILE_PB)   /* 112768 */
#define SMEM_TOTAL (SM_X1 + TILE_PB)  /* 182400 */

// async 16B-chunk copy of a 128x128 f32 tile into padded smem
__device__ __forceinline__ void load_tile_async(uint32_t sm_dst, const float* gsrc, int tid) {
#pragma unroll
    for (int i = 0; i < 16; i++) {
        int c = i * 256 + tid;            // 0..4095 16B chunks
        int row = c >> 5, u = c & 31;
        cp_async16(sm_dst + row * ROW_B + u * 16, gsrc + row * 128 + u * 4);
    }
}

// =========================== K0: init + W fragment pack ===========================
__global__ void k0_init(float* out, const float* __restrict__ W) {
    int i = blockIdx.x * blockDim.x + threadIdx.x;
    if (i < OUT_ELEMS) out[i] = 0.0f;
    if (i < NSEG) { g_segmax_u[i] = 0u; g_segsum[i] = 0.0f; }
    if (i < 8192) {
        // decode fragment coordinate
        int h  = i & 1;          // k-half (+8)
        int nb = (i >> 1) & 7;   // n8 block within warp's 64 cols
        int ln = (i >> 4) & 31;  // lane
        int st = (i >> 9) & 7;   // k16 step
        int wc = i >> 12;        // warp_c
        int r0 = ln >> 2, c0 = ln & 3;
        int n = 64 * wc + 8 * nb + r0;
        int k = 16 * st + 2 * c0 + 8 * h;
        uint32_t p = f16x2_pack(W[n * 128 + k], W[n * 128 + k + 1]);
        g_Wfrag[((wc * 8 + st) * 32 + ln) * 16 + nb * 2 + h] = p;
    }
    if (i == 0) g_tilectr = 0u;
}

// ============ K1: persistent fp16 GEMM + tanh + importance + segmax ============
__global__ __launch_bounds__(256, 1)
void k1_importance(const float* __restrict__ x,
                   const float* __restrict__ bv, const float* __restrict__ ctx,
                   const int* __restrict__ mask, const int* __restrict__ index) {
    extern __shared__ char smem[];
    uint32_t sbase = smem_u32(smem);
    int tid = threadIdx.x;
    int l = tid & 31, wid = tid >> 5;
    int warp_r = wid & 3;        // rows 32*warp_r .. +31
    int warp_c = wid >> 2;       // cols 64*warp_c .. +63
    int r0 = l >> 2, c0 = l & 3;
    int* smt = (int*)(smem + SM_T);

    if (tid < 128) {
        ((float*)(smem + SM_B))[tid]   = bv[tid];
        ((float*)(smem + SM_CTX))[tid] = ctx[tid];
    }
    if (tid == 0) smt[0] = (int)atomicAdd(&g_tilectr, 1u);
    __syncthreads();
    int t = smt[0];
    if (t >= NTILES) return;     // late CTA under work stealing

    // copy W fragments into padded smem (2048 x 16B)
#pragma unroll
    for (int i = 0; i < 8; i++) {
        int c = i * 256 + tid;
        int grp = c >> 2, off = c & 3;
        cp_async16(sbase + SM_WF + grp * 80 + off * 16, (const char*)g_Wfrag + c * 16);
    }
    load_tile_async(sbase + SM_X0, x + (size_t)t * 16384, tid);
    CP_COMMIT();

    // per-lane bases
    const int a_base = (32 * warp_r + r0) * ROWF + 2 * c0;        // f32 units
    const uint32_t wf_base = sbase + SM_WF + (uint32_t)((warp_c * 8) * 32 + l) * 80;
    const float* sb = (const float*)(smem + SM_B);
    const float* sc = (const float*)(smem + SM_CTX);
    float* pacc = (float*)(smem + SM_PACC);

    int pp = 0;
    for (;;) {
        if (tid == 0) smt[0] = (int)atomicAdd(&g_tilectr, 1u);
        __syncthreads();                       // smt visible; buf[pp^1] reads drained
        int tn = smt[0];
        bool pend = (tn < NTILES);
        if (pend) {
            load_tile_async(sbase + SM_X0 + (uint32_t)(pp ^ 1) * TILE_PB,
                            x + (size_t)tn * 16384, tid);
            CP_COMMIT();
            CP_WAIT(1);                        // current tile's group done
        } else {
            CP_WAIT(0);
        }
        __syncthreads();

        const float* Xp = (const float*)(smem + SM_X0 + (uint32_t)pp * TILE_PB);
        float d[2][8][4];
#pragma unroll
        for (int mb = 0; mb < 2; mb++)
#pragma unroll
            for (int nb = 0; nb < 8; nb++)
#pragma unroll
                for (int r = 0; r < 4; r++) d[mb][nb][r] = 0.0f;

#pragma unroll
        for (int st = 0; st < 8; st++) {       // 8 k16 steps
            // B fragments: 4x LDS.128 from fragment-packed smem
            uint32_t Bv[4][4];
            uint32_t ba = wf_base + (uint32_t)(st * 32) * 80;
#pragma unroll
            for (int q = 0; q < 4; q++)
                LDS128(Bv[q][0], Bv[q][1], Bv[q][2], Bv[q][3], ba + q * 16);
            // A fragments: paired f32 loads + cvt to f16x2
            uint32_t A[2][4];
#pragma unroll
            for (int mb = 0; mb < 2; mb++) {
                int ab = a_base + 16 * st + mb * (16 * ROWF);
                float2 p00 = *(const float2*)(Xp + ab);
                float2 p10 = *(const float2*)(Xp + ab + 8 * ROWF);
                float2 p01 = *(const float2*)(Xp + ab + 8);
                float2 p11 = *(const float2*)(Xp + ab + 8 * ROWF + 8);
                A[mb][0] = f16x2_pack(p00.x, p00.y);
                A[mb][1] = f16x2_pack(p10.x, p10.y);
                A[mb][2] = f16x2_pack(p01.x, p01.y);
                A[mb][3] = f16x2_pack(p11.x, p11.y);
            }
#pragma unroll
            for (int nb = 0; nb < 8; nb++) {
                uint32_t bb0 = Bv[nb >> 1][(nb & 1) * 2];
                uint32_t bb1 = Bv[nb >> 1][(nb & 1) * 2 + 1];
                MMA_F16(d[0][nb], A[0][0], A[0][1], A[0][2], A[0][3], bb0, bb1);
                MMA_F16(d[1][nb], A[1][0], A[1][1], A[1][2], A[1][3], bb0, bb1);
            }
        }

        // ---- epilogue: tanh + ctx-dot on fragments ----
        float acc[4] = {0.f, 0.f, 0.f, 0.f};   // [mb*2 + hi8]
#pragma unroll
        for (int mb = 0; mb < 2; mb++) {
#pragma unroll
            for (int nb = 0; nb < 8; nb++) {
                int cb = 64 * warp_c + nb * 8 + c0 * 2;
#pragma unroll
                for (int r = 0; r < 4; r++) {
                    int c = cb + (r & 1);
                    float pre = d[mb][nb][r] + sb[c];
                    float tt = __expf(2.0f * pre);                  // tanh = 1 - 2/(e^{2x}+1)
                    float th = 1.0f - __fdividef(2.0f, tt + 1.0f);  // safe at +-inf
                    acc[mb * 2 + (r >> 1)] = fmaf(sc[c], th, acc[mb * 2 + (r >> 1)]);
                }
            }
        }
#pragma unroll
        for (int s = 0; s < 4; s++) {
            acc[s] += __shfl_xor_sync(0xFFFFFFFFu, acc[s], 1);
            acc[s] += __shfl_xor_sync(0xFFFFFFFFu, acc[s], 2);
        }
        if (c0 == 0) {
#pragma unroll
            for (int s = 0; s < 4; s++) {
                int row = 32 * warp_r + 16 * (s >> 1) + 8 * (s & 1) + r0;
                pacc[row * 2 + warp_c] = acc[s];
            }
        }
        __syncthreads();

        if (tid < 128) {
            float impv = (pacc[tid * 2] + pacc[tid * 2 + 1]) * 0.08838834764831843f;
            int row = t * 128 + tid;
            if (mask[row] == 0) impv = -1e9f;
            g_imp[row] = impv;
            int seg = index[row];
            int bq = row / NSEQ;
            atomicMax(&g_segmax_u[bq * NIDX + seg], fenc(impv));
        }

        if (!pend) break;
        t = tn; pp ^= 1;
    }
}

// ============ K2: exp + segment sum ============
__global__ __launch_bounds__(256)
void k2_expsum(const int* __restrict__ index) {
    int row = blockIdx.x * blockDim.x + threadIdx.x;
    if (row >= ROWS) return;
    float impv = g_imp[row];
    int seg = index[row];
    int bq = row / NSEQ;
    float m = fdec(g_segmax_u[bq * NIDX + seg]);
    float e = __expf(impv - m);
    g_imp[row] = e;
    atomicAdd(&g_segsum[bq * NIDX + seg], e);
}

// ============ K3: weights + scatter-add of x (32 rows/warp, 2-way unrolled) ============
__global__ __launch_bounds__(256)
void k3_scatter(const float* __restrict__ x, const int* __restrict__ index,
                float* __restrict__ out) {
    int warp = (blockIdx.x << 3) + (threadIdx.x >> 5);   // 25000 warps
    int lane = threadIdx.x & 31;
    int rbase = warp * 32;                               // NSEQ % 32 == 0: no bq straddle
    int row = rbase + lane;

    float e  = g_imp[row];
    int seg  = index[row];
    int bq   = row / NSEQ;
    int segg = bq * NIDX + seg;
    float s  = g_segsum[segg];
    float w  = e / s;
    out[ATTN_OFF + row] = w;

    const float4* xb = (const float4*)x;
    unsigned act = __ballot_sync(0xFFFFFFFFu, w != 0.0f);
    while (act) {
        int i = __ffs(act) - 1;
        act &= (act - 1);
        int j = -1;
        if (act) { j = __ffs(act) - 1; act &= (act - 1); }
        int jj = (j < 0) ? 0 : j;
        float wi = __shfl_sync(0xFFFFFFFFu, w, i);
        int   si = __shfl_sync(0xFFFFFFFFu, segg, i);
        float wj = __shfl_sync(0xFFFFFFFFu, w, jj);
        int   sj = __shfl_sync(0xFFFFFFFFu, segg, jj);
        float4 vi = __ldg(xb + (size_t)(rbase + i) * 32 + lane);
        float4 vj;
        if (j >= 0) vj = __ldg(xb + (size_t)(rbase + j) * 32 + lane);
        float* di = out + ((size_t)si << 7) + lane * 4;
        asm volatile("red.global.add.v4.f32 [%0], {%1, %2, %3, %4};"
                     :: "l"(di), "f"(vi.x * wi), "f"(vi.y * wi), "f"(vi.z * wi), "f"(vi.w * wi)
                     : "memory");
        if (j >= 0) {
            float* dj = out + ((size_t)sj << 7) + lane * 4;
            asm volatile("red.global.add.v4.f32 [%0], {%1, %2, %3, %4};"
                         :: "l"(dj), "f"(vj.x * wj), "f"(vj.y * wj), "f"(vj.z * wj), "f"(vj.w * wj)
                         : "memory");
        }
    }
}

// ============================ launch ============================
extern "C" void kernel_launch(void* const* d_in, const int* in_sizes, int n_in,
                              void* d_out, int out_size) {
    const float* x     = (const float*)d_in[0];
    const float* W     = (const float*)d_in[1];
    const float* bv    = (const float*)d_in[2];
    const float* ctx   = (const float*)d_in[3];
    const int*   mask  = (const int*)d_in[4];
    const int*   index = (const int*)d_in[5];
    float* out = (float*)d_out;

    cudaFuncSetAttribute(k1_importance, cudaFuncAttributeMaxDynamicSharedMemorySize, SMEM_TOTAL);

    k0_init<<<(OUT_ELEMS + 255) / 256, 256>>>(out, W);
    k1_importance<<<152, 256, SMEM_TOTAL>>>(x, bv, ctx, mask, index);
    k2_expsum<<<(ROWS + 255) / 256, 256>>>(index);
    k3_scatter<<<(ROWS / 256), 256>>>(x, index, out);
}

// round 8
// speedup vs baseline: 2.3190x; 1.0714x over previous
#include <cuda_runtime.h>
#include <cuda_fp16.h>
#include <cstdint>

#define BQ    4
#define NSEQ  200000
#define EDIM  128
#define NIDX  2048
#define ROWS  (BQ * NSEQ)            /* 800000 */
#define NTILES (ROWS / 128)          /* 6250 exact */
#define OUT_ELEMS (BQ * NIDX * EDIM) /* 1048576 */
#define ATTN_OFF  OUT_ELEMS
#define NSEG (BQ * NIDX)             /* 8192 */

// ---------------- device scratch (no cudaMalloc allowed) ----------------
__device__ float    g_imp[ROWS];        // importance, then exp(imp - m)
__device__ unsigned g_segmax_u[NSEG];   // monotonic-encoded float max
__device__ float    g_segsum[NSEG];
__device__ uint32_t g_Wfrag[8192];      // W as fragment-ordered fp16x2 pairs (32 KB)
__device__ unsigned g_tilectr;          // work-stealing tile counter

// ---------------- helpers ----------------
__device__ __forceinline__ uint32_t smem_u32(const void* p) {
    uint32_t a;
    asm("{ .reg .u64 t; cvta.to.shared.u64 t, %1; cvt.u32.u64 %0, t; }" : "=r"(a) : "l"(p));
    return a;
}
// pack two f32 -> f16x2 (lo = first arg)
__device__ __forceinline__ uint32_t f16x2_pack(float lo, float hi) {
    uint32_t r;
    asm("cvt.rn.f16x2.f32 %0, %1, %2;" : "=r"(r) : "f"(hi), "f"(lo));
    return r;
}
__device__ __forceinline__ float tanh_approx(float f) {
    float r;
    asm("tanh.approx.f32 %0, %1;" : "=f"(r) : "f"(f));
    return r;
}
__device__ __forceinline__ void cp_async16(uint32_t dst, const void* src) {
    asm volatile("cp.async.cg.shared.global [%0], [%1], 16;" :: "r"(dst), "l"(src));
}
#define CP_COMMIT()  asm volatile("cp.async.commit_group;" ::: "memory")
#define CP_WAIT(N)   asm volatile("cp.async.wait_group %0;" :: "n"(N) : "memory")

#define LDS128(r0_, r1_, r2_, r3_, addr) \
    asm volatile("ld.shared.v4.u32 {%0,%1,%2,%3}, [%4];" \
        : "=r"(r0_), "=r"(r1_), "=r"(r2_), "=r"(r3_) : "r"(addr))

#define LDSM_X4(r0_, r1_, r2_, r3_, addr) \
    asm volatile("ldmatrix.sync.aligned.m8n8.x4.shared.b16 {%0,%1,%2,%3}, [%4];" \
        : "=r"(r0_), "=r"(r1_), "=r"(r2_), "=r"(r3_) : "r"(addr))

#define MMA_F16(d, a0, a1, a2, a3, b0, b1) \
    asm volatile("mma.sync.aligned.m16n8k16.row.col.f32.f16.f16.f32 " \
        "{%0,%1,%2,%3}, {%4,%5,%6,%7}, {%8,%9}, {%0,%1,%2,%3};" \
        : "+f"((d)[0]), "+f"((d)[1]), "+f"((d)[2]), "+f"((d)[3]) \
        : "r"(a0), "r"(a1), "r"(a2), "r"(a3), "r"(b0), "r"(b1))

// monotonic float<->uint for atomicMax
__device__ __forceinline__ unsigned fenc(float f) {
    unsigned u = __float_as_uint(f);
    return u ^ ((unsigned)((int)u >> 31) | 0x80000000u);
}
__device__ __forceinline__ float fdec(unsigned u) {
    unsigned v = (u & 0x80000000u) ? (u ^ 0x80000000u) : ~u;
    return __uint_as_float(v);
}

// ---------------- SMEM layout (K1) ----------------
// f32 staging: 128 rows x 136 f32 (544 B stride).
// f16 X tile: 128 rows x 136 f16 (272 B stride) -> conflict-free ldmatrix (proven R4).
// W frags:    [wc(2)][step(8)][lane(32)] x 64B payload padded to 80 B/lane.
#define ROWF      136
#define ROW_B     544
#define ROWH_B    272
#define TILE_PB   (128 * ROW_B)       /* 69632 */
#define XF16_PB   (128 * ROWH_B)      /* 34816 */
#define SM_B      0                   /* 512B bias   */
#define SM_CTX    512                 /* 512B ctx    */
#define SM_PACC   1024                /* 1024B       */
#define SM_T      2048                /* 16B tile broadcast */
#define SM_WF     2176                /* 40960B W fragments */
#define SM_XF16   (SM_WF + 40960)     /* 43136 */
#define SM_X0     (SM_XF16 + XF16_PB) /* 77952 */
#define SM_X1     (SM_X0 + TILE_PB)   /* 147584 */
#define SMEM_TOTAL (SM_X1 + TILE_PB)  /* 217216 */

// async 16B-chunk copy of a 128x128 f32 tile into padded smem
__device__ __forceinline__ void load_tile_async(uint32_t sm_dst, const float* gsrc, int tid) {
#pragma unroll
    for (int i = 0; i < 16; i++) {
        int c = i * 256 + tid;            // 0..4095 16B chunks
        int row = c >> 5, u = c & 31;
        cp_async16(sm_dst + row * ROW_B + u * 16, gsrc + row * 128 + u * 4);
    }
}

// =========================== K0: init + W fragment pack ===========================
__global__ void k0_init(float* out, const float* __restrict__ W) {
    int i = blockIdx.x * blockDim.x + threadIdx.x;
    if (i < OUT_ELEMS) out[i] = 0.0f;
    if (i < NSEG) { g_segmax_u[i] = 0u; g_segsum[i] = 0.0f; }
    if (i < 8192) {
        int h  = i & 1;          // k-half (+8)
        int nb = (i >> 1) & 7;   // n8 block within warp's 64 cols
        int ln = (i >> 4) & 31;  // lane
        int st = (i >> 9) & 7;   // k16 step
        int wc = i >> 12;        // warp_c
        int r0 = ln >> 2, c0 = ln & 3;
        int n = 64 * wc + 8 * nb + r0;
        int k = 16 * st + 2 * c0 + 8 * h;
        uint32_t p = f16x2_pack(W[n * 128 + k], W[n * 128 + k + 1]);
        g_Wfrag[((wc * 8 + st) * 32 + ln) * 16 + nb * 2 + h] = p;
    }
    if (i == 0) g_tilectr = 0u;
}

// ============ K1: persistent fp16 GEMM + tanh + importance + segmax ============
__global__ __launch_bounds__(256, 1)
void k1_importance(const float* __restrict__ x,
                   const float* __restrict__ bv, const float* __restrict__ ctx,
                   const int* __restrict__ mask, const int* __restrict__ index) {
    extern __shared__ char smem[];
    uint32_t sbase = smem_u32(smem);
    int tid = threadIdx.x;
    int l = tid & 31, wid = tid >> 5;
    int warp_r = wid & 3;        // rows 32*warp_r .. +31
    int warp_c = wid >> 2;       // cols 64*warp_c .. +63
    int r0 = l >> 2, c0 = l & 3;
    int* smt = (int*)(smem + SM_T);

    if (tid < 128) {
        ((float*)(smem + SM_B))[tid]   = bv[tid];
        ((float*)(smem + SM_CTX))[tid] = ctx[tid];
    }
    if (tid == 0) smt[0] = (int)atomicAdd(&g_tilectr, 1u);
    __syncthreads();
    int t = smt[0];
    if (t >= NTILES) return;     // late CTA under work stealing

    // copy W fragments into padded smem (2048 x 16B)
#pragma unroll
    for (int i = 0; i < 8; i++) {
        int c = i * 256 + tid;
        int grp = c >> 2, off = c & 3;
        cp_async16(sbase + SM_WF + grp * 80 + off * 16, (const char*)g_Wfrag + c * 16);
    }
    load_tile_async(sbase + SM_X0, x + (size_t)t * 16384, tid);
    CP_COMMIT();

    // per-lane bases
    const uint32_t a_sm = sbase + SM_XF16
                        + (uint32_t)(32 * warp_r + (l & 15)) * ROWH_B + ((l >> 4) << 4);
    const uint32_t wf_base = sbase + SM_WF + (uint32_t)((warp_c * 8) * 32 + l) * 80;
    const float* sb = (const float*)(smem + SM_B);
    const float* sc = (const float*)(smem + SM_CTX);
    float* pacc = (float*)(smem + SM_PACC);

    int pp = 0;
    for (;;) {
        if (tid == 0) smt[0] = (int)atomicAdd(&g_tilectr, 1u);
        __syncthreads();                       // smt visible; prev xf16 reads drained
        int tn = smt[0];
        bool pend = (tn < NTILES);
        if (pend) {
            load_tile_async(sbase + SM_X0 + (uint32_t)(pp ^ 1) * TILE_PB,
                            x + (size_t)tn * 16384, tid);
            CP_COMMIT();
            CP_WAIT(1);                        // current tile's group done
        } else {
            CP_WAIT(0);
        }
        __syncthreads();

        // ---- convert pass: staging f32 -> shared f16 tile (once per CTA) ----
        {
            const char* Sp = smem + SM_X0 + (uint32_t)pp * TILE_PB;
            char* Hp = smem + SM_XF16;
#pragma unroll
            for (int i = 0; i < 16; i++) {
                int c = i * 256 + tid;
                int row = c >> 5, u = c & 31;
                float4 v = *(const float4*)(Sp + row * ROW_B + u * 16);
                uint2 p;
                p.x = f16x2_pack(v.x, v.y);
                p.y = f16x2_pack(v.z, v.w);
                *(uint2*)(Hp + row * ROWH_B + u * 8) = p;
            }
        }
        __syncthreads();

        float d[2][8][4];
#pragma unroll
        for (int mb = 0; mb < 2; mb++)
#pragma unroll
            for (int nb = 0; nb < 8; nb++)
#pragma unroll
                for (int r = 0; r < 4; r++) d[mb][nb][r] = 0.0f;

#pragma unroll
        for (int st = 0; st < 8; st++) {       // 8 k16 steps (32B each along row)
            uint32_t A[2][4];
            LDSM_X4(A[0][0], A[0][1], A[0][2], A[0][3], a_sm + st * 32);
            LDSM_X4(A[1][0], A[1][1], A[1][2], A[1][3], a_sm + st * 32 + 16 * ROWH_B);
            uint32_t Bv[4][4];
            uint32_t ba = wf_base + (uint32_t)(st * 32) * 80;
#pragma unroll
            for (int q = 0; q < 4; q++)
                LDS128(Bv[q][0], Bv[q][1], Bv[q][2], Bv[q][3], ba + q * 16);
#pragma unroll
            for (int nb = 0; nb < 8; nb++) {
                uint32_t bb0 = Bv[nb >> 1][(nb & 1) * 2];
                uint32_t bb1 = Bv[nb >> 1][(nb & 1) * 2 + 1];
                MMA_F16(d[0][nb], A[0][0], A[0][1], A[0][2], A[0][3], bb0, bb1);
                MMA_F16(d[1][nb], A[1][0], A[1][1], A[1][2], A[1][3], bb0, bb1);
            }
        }

        // ---- epilogue: tanh.approx + ctx-dot on fragments ----
        float acc[4] = {0.f, 0.f, 0.f, 0.f};   // [mb*2 + hi8]
#pragma unroll
        for (int mb = 0; mb < 2; mb++) {
#pragma unroll
            for (int nb = 0; nb < 8; nb++) {
                int cb = 64 * warp_c + nb * 8 + c0 * 2;
#pragma unroll
                for (int r = 0; r < 4; r++) {
                    int c = cb + (r & 1);
                    float th = tanh_approx(d[mb][nb][r] + sb[c]);
                    acc[mb * 2 + (r >> 1)] = fmaf(sc[c], th, acc[mb * 2 + (r >> 1)]);
                }
            }
        }
#pragma unroll
        for (int s = 0; s < 4; s++) {
            acc[s] += __shfl_xor_sync(0xFFFFFFFFu, acc[s], 1);
            acc[s] += __shfl_xor_sync(0xFFFFFFFFu, acc[s], 2);
        }
        if (c0 == 0) {
#pragma unroll
            for (int s = 0; s < 4; s++) {
                int row = 32 * warp_r + 16 * (s >> 1) + 8 * (s & 1) + r0;
                pacc[row * 2 + warp_c] = acc[s];
            }
        }
        __syncthreads();

        if (tid < 128) {
            float impv = (pacc[tid * 2] + pacc[tid * 2 + 1]) * 0.08838834764831843f;
            int row = t * 128 + tid;
            if (mask[row] == 0) impv = -1e9f;
            g_imp[row] = impv;
            int seg = index[row];
            int bq = row / NSEQ;
            atomicMax(&g_segmax_u[bq * NIDX + seg], fenc(impv));
        }

        if (!pend) break;
        t = tn; pp ^= 1;
    }
}

// ============ K2: exp + segment sum ============
__global__ __launch_bounds__(256)
void k2_expsum(const int* __restrict__ index) {
    int row = blockIdx.x * blockDim.x + threadIdx.x;
    if (row >= ROWS) return;
    float impv = g_imp[row];
    int seg = index[row];
    int bq = row / NSEQ;
    float m = fdec(g_segmax_u[bq * NIDX + seg]);
    float e = __expf(impv - m);
    g_imp[row] = e;
    atomicAdd(&g_segsum[bq * NIDX + seg], e);
}

// ============ K3: weights + scatter-add of x (32 rows/warp, 4-way unrolled) ============
__global__ __launch_bounds__(256)
void k3_scatter(const float* __restrict__ x, const int* __restrict__ index,
                float* __restrict__ out) {
    int warp = (blockIdx.x << 3) + (threadIdx.x >> 5);   // 25000 warps
    int lane = threadIdx.x & 31;
    int rbase = warp * 32;                               // NSEQ % 32 == 0: no bq straddle
    int row = rbase + lane;

    float e  = g_imp[row];
    int seg  = index[row];
    int bq   = row / NSEQ;
    int segg = bq * NIDX + seg;
    float s  = g_segsum[segg];
    float w  = e / s;
    out[ATTN_OFF + row] = w;

    const float4* xb = (const float4*)x;
    unsigned act = __ballot_sync(0xFFFFFFFFu, w != 0.0f);
    while (act) {
        int i0 = __ffs(act) - 1;             act &= (act - 1);
        int i1 = act ? __ffs(act) - 1 : -1;  if (i1 >= 0) act &= (act - 1);
        int i2 = act ? __ffs(act) - 1 : -1;  if (i2 >= 0) act &= (act - 1);
        int i3 = act ? __ffs(act) - 1 : -1;  if (i3 >= 0) act &= (act - 1);
        int j1 = i1 < 0 ? 0 : i1, j2 = i2 < 0 ? 0 : i2, j3 = i3 < 0 ? 0 : i3;
        float w0 = __shfl_sync(0xFFFFFFFFu, w, i0);
        float w1 = __shfl_sync(0xFFFFFFFFu, w, j1);
        float w2 = __shfl_sync(0xFFFFFFFFu, w, j2);
        float w3 = __shfl_sync(0xFFFFFFFFu, w, j3);
        int   s0 = __shfl_sync(0xFFFFFFFFu, segg, i0);
        int   s1 = __shfl_sync(0xFFFFFFFFu, segg, j1);
        int   s2 = __shfl_sync(0xFFFFFFFFu, segg, j2);
        int   s3 = __shfl_sync(0xFFFFFFFFu, segg, j3);
        float4 v0 = __ldg(xb + (size_t)(rbase + i0) * 32 + lane);
        float4 v1, v2, v3;
        if (i1 >= 0) v1 = __ldg(xb + (size_t)(rbase + i1) * 32 + lane);
        if (i2 >= 0) v2 = __ldg(xb + (size_t)(rbase + i2) * 32 + lane);
        if (i3 >= 0) v3 = __ldg(xb + (size_t)(rbase + i3) * 32 + lane);
        float* d0 = out + ((size_t)s0 << 7) + lane * 4;
        asm volatile("red.global.add.v4.f32 [%0], {%1, %2, %3, %4};"
                     :: "l"(d0), "f"(v0.x * w0), "f"(v0.y * w0), "f"(v0.z * w0), "f"(v0.w * w0)
                     : "memory");
        if (i1 >= 0) {
            float* d1 = out + ((size_t)s1 << 7) + lane * 4;
            asm volatile("red.global.add.v4.f32 [%0], {%1, %2, %3, %4};"
                         :: "l"(d1), "f"(v1.x * w1), "f"(v1.y * w1), "f"(v1.z * w1), "f"(v1.w * w1)
                         : "memory");
        }
        if (i2 >= 0) {
            float* d2 = out + ((size_t)s2 << 7) + lane * 4;
            asm volatile("red.global.add.v4.f32 [%0], {%1, %2, %3, %4};"
                         :: "l"(d2), "f"(v2.x * w2), "f"(v2.y * w2), "f"(v2.z * w2), "f"(v2.w * w2)
                         : "memory");
        }
        if (i3 >= 0) {
            float* d3 = out + ((size_t)s3 << 7) + lane * 4;
            asm volatile("red.global.add.v4.f32 [%0], {%1, %2, %3, %4};"
                         :: "l"(d3), "f"(v3.x * w3), "f"(v3.y * w3), "f"(v3.z * w3), "f"(v3.w * w3)
                         : "memory");
        }
    }
}

// ============================ launch ============================
extern "C" void kernel_launch(void* const* d_in, const int* in_sizes, int n_in,
                              void* d_out, int out_size) {
    const float* x     = (const float*)d_in[0];
    const float* W     = (const float*)d_in[1];
    const float* bv    = (const float*)d_in[2];
    const float* ctx   = (const float*)d_in[3];
    const int*   mask  = (const int*)d_in[4];
    const int*   index = (const int*)d_in[5];
    float* out = (float*)d_out;

    cudaFuncSetAttribute(k1_importance, cudaFuncAttributeMaxDynamicSharedMemorySize, SMEM_TOTAL);

    k0_init<<<(OUT_ELEMS + 255) / 256, 256>>>(out, W);
    k1_importance<<<152, 256, SMEM_TOTAL>>>(x, bv, ctx, mask, index);
    k2_expsum<<<(ROWS + 255) / 256, 256>>>(index);
    k3_scatter<<<(ROWS / 256), 256>>>(x, index, out);
}

// round 9
// speedup vs baseline: 2.5726x; 1.1093x over previous
#include <cuda_runtime.h>
#include <cuda_fp16.h>
#include <cstdint>

#define BQ    4
#define NSEQ  200000
#define EDIM  128
#define NIDX  2048
#define ROWS  (BQ * NSEQ)            /* 800000 */
#define NTILES (ROWS / 128)          /* 6250 exact */
#define OUT_ELEMS (BQ * NIDX * EDIM) /* 1048576 */
#define ATTN_OFF  OUT_ELEMS
#define NSEG (BQ * NIDX)             /* 8192 */

// ---------------- device scratch (no cudaMalloc allowed) ----------------
__device__ float    g_imp[ROWS];        // importance, then exp(imp - m)
__device__ unsigned g_segmax_u[NSEG];   // monotonic-encoded float max
__device__ float    g_segsum[NSEG];
__device__ uint32_t g_Wfrag[8192];      // W as fragment-ordered fp16x2 pairs (32 KB)
__device__ unsigned g_tilectr;          // work-stealing tile counter

// ---------------- helpers ----------------
__device__ __forceinline__ uint32_t smem_u32(const void* p) {
    uint32_t a;
    asm("{ .reg .u64 t; cvta.to.shared.u64 t, %1; cvt.u32.u64 %0, t; }" : "=r"(a) : "l"(p));
    return a;
}
// pack two f32 -> f16x2 (lo = first arg)
__device__ __forceinline__ uint32_t f16x2_pack(float lo, float hi) {
    uint32_t r;
    asm("cvt.rn.f16x2.f32 %0, %1, %2;" : "=r"(r) : "f"(hi), "f"(lo));
    return r;
}
__device__ __forceinline__ float tanh_approx(float f) {
    float r;
    asm("tanh.approx.f32 %0, %1;" : "=f"(r) : "f"(f));
    return r;
}
__device__ __forceinline__ void cp_async16(uint32_t dst, const void* src) {
    asm volatile("cp.async.cg.shared.global [%0], [%1], 16;" :: "r"(dst), "l"(src));
}
#define CP_COMMIT()  asm volatile("cp.async.commit_group;" ::: "memory")
#define CP_WAIT(N)   asm volatile("cp.async.wait_group %0;" :: "n"(N) : "memory")

#define LDS128(r0_, r1_, r2_, r3_, addr) \
    asm volatile("ld.shared.v4.u32 {%0,%1,%2,%3}, [%4];" \
        : "=r"(r0_), "=r"(r1_), "=r"(r2_), "=r"(r3_) : "r"(addr))

#define LDSM_X4(r0_, r1_, r2_, r3_, addr) \
    asm volatile("ldmatrix.sync.aligned.m8n8.x4.shared.b16 {%0,%1,%2,%3}, [%4];" \
        : "=r"(r0_), "=r"(r1_), "=r"(r2_), "=r"(r3_) : "r"(addr))

#define MMA_F16(d, a0, a1, a2, a3, b0, b1) \
    asm volatile("mma.sync.aligned.m16n8k16.row.col.f32.f16.f16.f32 " \
        "{%0,%1,%2,%3}, {%4,%5,%6,%7}, {%8,%9}, {%0,%1,%2,%3};" \
        : "+f"((d)[0]), "+f"((d)[1]), "+f"((d)[2]), "+f"((d)[3]) \
        : "r"(a0), "r"(a1), "r"(a2), "r"(a3), "r"(b0), "r"(b1))

// monotonic float<->uint for atomicMax
__device__ __forceinline__ unsigned fenc(float f) {
    unsigned u = __float_as_uint(f);
    return u ^ ((unsigned)((int)u >> 31) | 0x80000000u);
}
__device__ __forceinline__ float fdec(unsigned u) {
    unsigned v = (u & 0x80000000u) ? (u ^ 0x80000000u) : ~u;
    return __uint_as_float(v);
}

// ---------------- SMEM layout (K1) ----------------
// f16 X tile: 128 rows x 136 f16 (272 B stride) -> conflict-free ldmatrix.
// W frags:    [wc(2)][step(8)][lane(32)] x 64B payload padded to 80 B/lane.
#define ROWH_B    272
#define XF16_PB   (128 * ROWH_B)      /* 34816 */
#define SM_B      0                   /* 512B bias   */
#define SM_CTX    512                 /* 512B ctx    */
#define SM_PACC   1024                /* 1024B       */
#define SM_T      2048                /* 16B tile broadcast */
#define SM_WF     2176                /* 40960B W fragments */
#define SM_XF16   (SM_WF + 40960)     /* 43136 */
#define SMEM_TOTAL (SM_XF16 + XF16_PB) /* 77952 */

// =========================== K0: init + W fragment pack ===========================
__global__ void k0_init(float* out, const float* __restrict__ W) {
    int i = blockIdx.x * blockDim.x + threadIdx.x;
    if (i < OUT_ELEMS) out[i] = 0.0f;
    if (i < NSEG) { g_segmax_u[i] = 0u; g_segsum[i] = 0.0f; }
    if (i < 8192) {
        int h  = i & 1;          // k-half (+8)
        int nb = (i >> 1) & 7;   // n8 block within warp's 64 cols
        int ln = (i >> 4) & 31;  // lane
        int st = (i >> 9) & 7;   // k16 step
        int wc = i >> 12;        // warp_c
        int r0 = ln >> 2, c0 = ln & 3;
        int n = 64 * wc + 8 * nb + r0;
        int k = 16 * st + 2 * c0 + 8 * h;
        uint32_t p = f16x2_pack(W[n * 128 + k], W[n * 128 + k + 1]);
        g_Wfrag[((wc * 8 + st) * 32 + ln) * 16 + nb * 2 + h] = p;
    }
    if (i == 0) g_tilectr = 0u;
}

// ============ K1: persistent fp16 GEMM + tanh + importance + segmax ============
// Register-prefetch pipeline: LDG next x-tile into regs under the current MMA loop,
// convert+STS f16 at the top of the next iteration (no f32 smem staging).
__global__ __launch_bounds__(256, 1)
void k1_importance(const float* __restrict__ x,
                   const float* __restrict__ bv, const float* __restrict__ ctx,
                   const int* __restrict__ mask, const int* __restrict__ index) {
    extern __shared__ char smem[];
    uint32_t sbase = smem_u32(smem);
    int tid = threadIdx.x;
    int l = tid & 31, wid = tid >> 5;
    int warp_r = wid & 3;        // rows 32*warp_r .. +31
    int warp_c = wid >> 2;       // cols 64*warp_c .. +63
    int r0 = l >> 2, c0 = l & 3;
    int* smt = (int*)(smem + SM_T);

    if (tid < 128) {
        ((float*)(smem + SM_B))[tid]   = bv[tid];
        ((float*)(smem + SM_CTX))[tid] = ctx[tid];
    }
    if (tid == 0) smt[0] = (int)atomicAdd(&g_tilectr, 1u);
    __syncthreads();
    int t = smt[0];
    if (t >= NTILES) return;     // late CTA under work stealing (uniform per CTA)

    // copy W fragments into padded smem (2048 x 16B)
#pragma unroll
    for (int i = 0; i < 8; i++) {
        int c = i * 256 + tid;
        int grp = c >> 2, off = c & 3;
        cp_async16(sbase + SM_WF + grp * 80 + off * 16, (const char*)g_Wfrag + c * 16);
    }
    CP_COMMIT();

    // prefetch first x tile into registers
    const float4* xb = (const float4*)x;
    float4 xr[16];
#pragma unroll
    for (int i = 0; i < 16; i++)
        xr[i] = __ldg(xb + (size_t)t * 4096 + i * 256 + tid);

    CP_WAIT(0);   // own W chunks done; cross-thread visibility via in-loop sync

    // per-lane bases
    const uint32_t a_sm = sbase + SM_XF16
                        + (uint32_t)(32 * warp_r + (l & 15)) * ROWH_B + ((l >> 4) << 4);
    const uint32_t wf_base = sbase + SM_WF + (uint32_t)((warp_c * 8) * 32 + l) * 80;
    const float* sb = (const float*)(smem + SM_B);
    const float* sc = (const float*)(smem + SM_CTX);
    float* pacc = (float*)(smem + SM_PACC);
    char* Hp = smem + SM_XF16;

    for (;;) {
        // ---- convert + store current tile's x (from regs) into shared f16 ----
#pragma unroll
        for (int i = 0; i < 16; i++) {
            int c = i * 256 + tid;
            int row = c >> 5, u = c & 31;
            uint2 p;
            p.x = f16x2_pack(xr[i].x, xr[i].y);
            p.y = f16x2_pack(xr[i].z, xr[i].w);
            *(uint2*)(Hp + row * ROWH_B + u * 8) = p;
        }
        if (tid == 0) smt[0] = (int)atomicAdd(&g_tilectr, 1u);
        __syncthreads();                       // STS visible; smt visible; W visible (1st iter)
        int tn = smt[0];
        bool pend = (tn < NTILES);
        if (pend) {                            // prefetch next tile; hidden under MMA loop
#pragma unroll
            for (int i = 0; i < 16; i++)
                xr[i] = __ldg(xb + (size_t)tn * 4096 + i * 256 + tid);
        }

        float d[2][8][4];
#pragma unroll
        for (int mb = 0; mb < 2; mb++)
#pragma unroll
            for (int nb = 0; nb < 8; nb++)
#pragma unroll
                for (int r = 0; r < 4; r++) d[mb][nb][r] = 0.0f;

#pragma unroll
        for (int st = 0; st < 8; st++) {       // 8 k16 steps (32B each along row)
            uint32_t A[2][4];
            LDSM_X4(A[0][0], A[0][1], A[0][2], A[0][3], a_sm + st * 32);
            LDSM_X4(A[1][0], A[1][1], A[1][2], A[1][3], a_sm + st * 32 + 16 * ROWH_B);
            uint32_t Bv[4][4];
            uint32_t ba = wf_base + (uint32_t)(st * 32) * 80;
#pragma unroll
            for (int q = 0; q < 4; q++)
                LDS128(Bv[q][0], Bv[q][1], Bv[q][2], Bv[q][3], ba + q * 16);
#pragma unroll
            for (int nb = 0; nb < 8; nb++) {
                uint32_t bb0 = Bv[nb >> 1][(nb & 1) * 2];
                uint32_t bb1 = Bv[nb >> 1][(nb & 1) * 2 + 1];
                MMA_F16(d[0][nb], A[0][0], A[0][1], A[0][2], A[0][3], bb0, bb1);
                MMA_F16(d[1][nb], A[1][0], A[1][1], A[1][2], A[1][3], bb0, bb1);
            }
        }

        // ---- epilogue: tanh.approx + ctx-dot on fragments ----
        float acc[4] = {0.f, 0.f, 0.f, 0.f};   // [mb*2 + hi8]
#pragma unroll
        for (int mb = 0; mb < 2; mb++) {
#pragma unroll
            for (int nb = 0; nb < 8; nb++) {
                int cb = 64 * warp_c + nb * 8 + c0 * 2;
#pragma unroll
                for (int r = 0; r < 4; r++) {
                    int c = cb + (r & 1);
                    float th = tanh_approx(d[mb][nb][r] + sb[c]);
                    acc[mb * 2 + (r >> 1)] = fmaf(sc[c], th, acc[mb * 2 + (r >> 1)]);
                }
            }
        }
#pragma unroll
        for (int s = 0; s < 4; s++) {
            acc[s] += __shfl_xor_sync(0xFFFFFFFFu, acc[s], 1);
            acc[s] += __shfl_xor_sync(0xFFFFFFFFu, acc[s], 2);
        }
        if (c0 == 0) {
#pragma unroll
            for (int s = 0; s < 4; s++) {
                int row = 32 * warp_r + 16 * (s >> 1) + 8 * (s & 1) + r0;
                pacc[row * 2 + warp_c] = acc[s];
            }
        }
        __syncthreads();   // pacc ready; also: all Xf16 reads done before next STS

        if (tid < 128) {
            float impv = (pacc[tid * 2] + pacc[tid * 2 + 1]) * 0.08838834764831843f;
            int row = t * 128 + tid;
            if (mask[row] == 0) impv = -1e9f;
            g_imp[row] = impv;
            int seg = index[row];
            int bq = row / NSEQ;
            atomicMax(&g_segmax_u[bq * NIDX + seg], fenc(impv));
        }

        if (!pend) break;
        t = tn;
    }
}

// ============ K2: exp + segment sum ============
__global__ __launch_bounds__(256)
void k2_expsum(const int* __restrict__ index) {
    int row = blockIdx.x * blockDim.x + threadIdx.x;
    if (row >= ROWS) return;
    float impv = g_imp[row];
    int seg = index[row];
    int bq = row / NSEQ;
    float m = fdec(g_segmax_u[bq * NIDX + seg]);
    float e = __expf(impv - m);
    g_imp[row] = e;
    atomicAdd(&g_segsum[bq * NIDX + seg], e);
}

// ============ K3: weights + scatter-add of x (32 rows/warp, 4-way unrolled) ============
__global__ __launch_bounds__(256)
void k3_scatter(const float* __restrict__ x, const int* __restrict__ index,
                float* __restrict__ out) {
    int warp = (blockIdx.x << 3) + (threadIdx.x >> 5);   // 25000 warps
    int lane = threadIdx.x & 31;
    int rbase = warp * 32;                               // NSEQ % 32 == 0: no bq straddle
    int row = rbase + lane;

    float e  = g_imp[row];
    int seg  = index[row];
    int bq   = row / NSEQ;
    int segg = bq * NIDX + seg;
    float s  = g_segsum[segg];
    float w  = e / s;
    out[ATTN_OFF + row] = w;

    const float4* xb = (const float4*)x;
    unsigned act = __ballot_sync(0xFFFFFFFFu, w != 0.0f);
    while (act) {
        int i0 = __ffs(act) - 1;             act &= (act - 1);
        int i1 = act ? __ffs(act) - 1 : -1;  if (i1 >= 0) act &= (act - 1);
        int i2 = act ? __ffs(act) - 1 : -1;  if (i2 >= 0) act &= (act - 1);
        int i3 = act ? __ffs(act) - 1 : -1;  if (i3 >= 0) act &= (act - 1);
        int j1 = i1 < 0 ? 0 : i1, j2 = i2 < 0 ? 0 : i2, j3 = i3 < 0 ? 0 : i3;
        float w0 = __shfl_sync(0xFFFFFFFFu, w, i0);
        float w1 = __shfl_sync(0xFFFFFFFFu, w, j1);
        float w2 = __shfl_sync(0xFFFFFFFFu, w, j2);
        float w3 = __shfl_sync(0xFFFFFFFFu, w, j3);
        int   s0 = __shfl_sync(0xFFFFFFFFu, segg, i0);
        int   s1 = __shfl_sync(0xFFFFFFFFu, segg, j1);
        int   s2 = __shfl_sync(0xFFFFFFFFu, segg, j2);
        int   s3 = __shfl_sync(0xFFFFFFFFu, segg, j3);
        float4 v0 = __ldg(xb + (size_t)(rbase + i0) * 32 + lane);
        float4 v1, v2, v3;
        if (i1 >= 0) v1 = __ldg(xb + (size_t)(rbase + i1) * 32 + lane);
        if (i2 >= 0) v2 = __ldg(xb + (size_t)(rbase + i2) * 32 + lane);
        if (i3 >= 0) v3 = __ldg(xb + (size_t)(rbase + i3) * 32 + lane);
        float* d0 = out + ((size_t)s0 << 7) + lane * 4;
        asm volatile("red.global.add.v4.f32 [%0], {%1, %2, %3, %4};"
                     :: "l"(d0), "f"(v0.x * w0), "f"(v0.y * w0), "f"(v0.z * w0), "f"(v0.w * w0)
                     : "memory");
        if (i1 >= 0) {
            float* d1 = out + ((size_t)s1 << 7) + lane * 4;
            asm volatile("red.global.add.v4.f32 [%0], {%1, %2, %3, %4};"
                         :: "l"(d1), "f"(v1.x * w1), "f"(v1.y * w1), "f"(v1.z * w1), "f"(v1.w * w1)
                         : "memory");
        }
        if (i2 >= 0) {
            float* d2 = out + ((size_t)s2 << 7) + lane * 4;
            asm volatile("red.global.add.v4.f32 [%0], {%1, %2, %3, %4};"
                         :: "l"(d2), "f"(v2.x * w2), "f"(v2.y * w2), "f"(v2.z * w2), "f"(v2.w * w2)
                         : "memory");
        }
        if (i3 >= 0) {
            float* d3 = out + ((size_t)s3 << 7) + lane * 4;
            asm volatile("red.global.add.v4.f32 [%0], {%1, %2, %3, %4};"
                         :: "l"(d3), "f"(v3.x * w3), "f"(v3.y * w3), "f"(v3.z * w3), "f"(v3.w * w3)
                         : "memory");
        }
    }
}

// ============================ launch ============================
extern "C" void kernel_launch(void* const* d_in, const int* in_sizes, int n_in,
                              void* d_out, int out_size) {
    const float* x     = (const float*)d_in[0];
    const float* W     = (const float*)d_in[1];
    const float* bv    = (const float*)d_in[2];
    const float* ctx   = (const float*)d_in[3];
    const int*   mask  = (const int*)d_in[4];
    const int*   index = (const int*)d_in[5];
    float* out = (float*)d_out;

    cudaFuncSetAttribute(k1_importance, cudaFuncAttributeMaxDynamicSharedMemorySize, SMEM_TOTAL);

    k0_init<<<(OUT_ELEMS + 255) / 256, 256>>>(out, W);
    k1_importance<<<152, 256, SMEM_TOTAL>>>(x, bv, ctx, mask, index);
    k2_expsum<<<(ROWS + 255) / 256, 256>>>(index);
    k3_scatter<<<(ROWS / 256), 256>>>(x, index, out);
}

// round 10
// speedup vs baseline: 2.6739x; 1.0394x over previous
#include <cuda_runtime.h>
#include <cuda_fp16.h>
#include <cstdint>

#define BQ    4
#define NSEQ  200000
#define EDIM  128
#define NIDX  2048
#define ROWS  (BQ * NSEQ)            /* 800000 */
#define NTILES (ROWS / 128)          /* 6250 exact */
#define OUT_ELEMS (BQ * NIDX * EDIM) /* 1048576 */
#define ATTN_OFF  OUT_ELEMS
#define NSEG (BQ * NIDX)             /* 8192 */

// ---------------- device scratch (no cudaMalloc allowed) ----------------
__device__ float    g_imp[ROWS];        // exp(importance)  (0 for masked rows)
__device__ float    g_segsum[NSEG];
__device__ uint32_t g_Wfrag[8192];      // W as fragment-ordered fp16x2 pairs (32 KB)
__device__ unsigned g_tilectr;          // work-stealing tile counter

// ---------------- helpers ----------------
__device__ __forceinline__ uint32_t smem_u32(const void* p) {
    uint32_t a;
    asm("{ .reg .u64 t; cvta.to.shared.u64 t, %1; cvt.u32.u64 %0, t; }" : "=r"(a) : "l"(p));
    return a;
}
// pack two f32 -> f16x2 (lo = first arg)
__device__ __forceinline__ uint32_t f16x2_pack(float lo, float hi) {
    uint32_t r;
    asm("cvt.rn.f16x2.f32 %0, %1, %2;" : "=r"(r) : "f"(hi), "f"(lo));
    return r;
}
__device__ __forceinline__ float tanh_approx(float f) {
    float r;
    asm("tanh.approx.f32 %0, %1;" : "=f"(r) : "f"(f));
    return r;
}
__device__ __forceinline__ void cp_async16(uint32_t dst, const void* src) {
    asm volatile("cp.async.cg.shared.global [%0], [%1], 16;" :: "r"(dst), "l"(src));
}
#define CP_COMMIT()  asm volatile("cp.async.commit_group;" ::: "memory")
#define CP_WAIT(N)   asm volatile("cp.async.wait_group %0;" :: "n"(N) : "memory")

#define LDS128(r0_, r1_, r2_, r3_, addr) \
    asm volatile("ld.shared.v4.u32 {%0,%1,%2,%3}, [%4];" \
        : "=r"(r0_), "=r"(r1_), "=r"(r2_), "=r"(r3_) : "r"(addr))

#define LDSM_X4(r0_, r1_, r2_, r3_, addr) \
    asm volatile("ldmatrix.sync.aligned.m8n8.x4.shared.b16 {%0,%1,%2,%3}, [%4];" \
        : "=r"(r0_), "=r"(r1_), "=r"(r2_), "=r"(r3_) : "r"(addr))

#define MMA_F16(d, a0, a1, a2, a3, b0, b1) \
    asm volatile("mma.sync.aligned.m16n8k16.row.col.f32.f16.f16.f32 " \
        "{%0,%1,%2,%3}, {%4,%5,%6,%7}, {%8,%9}, {%0,%1,%2,%3};" \
        : "+f"((d)[0]), "+f"((d)[1]), "+f"((d)[2]), "+f"((d)[3]) \
        : "r"(a0), "r"(a1), "r"(a2), "r"(a3), "r"(b0), "r"(b1))

// ---------------- SMEM layout (K1) ----------------
// f16 X tile: 128 rows x 136 f16 (272 B stride) -> conflict-free ldmatrix.
// W frags:    [wc(2)][step(8)][lane(32)] x 64B payload padded to 80 B/lane.
#define ROWH_B    272
#define XF16_PB   (128 * ROWH_B)      /* 34816 */
#define SM_B      0                   /* 512B bias   */
#define SM_CTX    512                 /* 512B ctx    */
#define SM_PACC   1024                /* 1024B       */
#define SM_T      2048                /* 16B tile broadcast */
#define SM_WF     2176                /* 40960B W fragments */
#define SM_XF16   (SM_WF + 40960)     /* 43136 */
#define SMEM_TOTAL (SM_XF16 + XF16_PB) /* 77952 */

// =========================== K0: init + W fragment pack ===========================
__global__ void k0_init(float* out, const float* __restrict__ W) {
    int i = blockIdx.x * blockDim.x + threadIdx.x;
    if (i < OUT_ELEMS) out[i] = 0.0f;
    if (i < NSEG) g_segsum[i] = 0.0f;
    if (i < 8192) {
        int h  = i & 1;          // k-half (+8)
        int nb = (i >> 1) & 7;   // n8 block within warp's 64 cols
        int ln = (i >> 4) & 31;  // lane
        int st = (i >> 9) & 7;   // k16 step
        int wc = i >> 12;        // warp_c
        int r0 = ln >> 2, c0 = ln & 3;
        int n = 64 * wc + 8 * nb + r0;
        int k = 16 * st + 2 * c0 + 8 * h;
        uint32_t p = f16x2_pack(W[n * 128 + k], W[n * 128 + k + 1]);
        g_Wfrag[((wc * 8 + st) * 32 + ln) * 16 + nb * 2 + h] = p;
    }
    if (i == 0) g_tilectr = 0u;
}

// ============ K1: persistent fp16 GEMM + tanh + exp(importance) + segsum ============
// No max-subtraction: importance is bounded (|imp| <= ~9), exp() cannot overflow;
// masked rows get exp(-1e9) == 0 exactly. Segment softmax = e / segsum(e).
__global__ __launch_bounds__(256, 1)
void k1_importance(const float* __restrict__ x,
                   const float* __restrict__ bv, const float* __restrict__ ctx,
                   const int* __restrict__ mask, const int* __restrict__ index) {
    extern __shared__ char smem[];
    uint32_t sbase = smem_u32(smem);
    int tid = threadIdx.x;
    int l = tid & 31, wid = tid >> 5;
    int warp_r = wid & 3;        // rows 32*warp_r .. +31
    int warp_c = wid >> 2;       // cols 64*warp_c .. +63
    int r0 = l >> 2, c0 = l & 3;
    int* smt = (int*)(smem + SM_T);

    if (tid < 128) {
        ((float*)(smem + SM_B))[tid]   = bv[tid];
        ((float*)(smem + SM_CTX))[tid] = ctx[tid];
    }
    if (tid == 0) smt[0] = (int)atomicAdd(&g_tilectr, 1u);
    __syncthreads();
    int t = smt[0];
    if (t >= NTILES) return;     // late CTA under work stealing (uniform per CTA)

    // copy W fragments into padded smem (2048 x 16B)
#pragma unroll
    for (int i = 0; i < 8; i++) {
        int c = i * 256 + tid;
        int grp = c >> 2, off = c & 3;
        cp_async16(sbase + SM_WF + grp * 80 + off * 16, (const char*)g_Wfrag + c * 16);
    }
    CP_COMMIT();

    // prefetch first x tile into registers
    const float4* xb = (const float4*)x;
    float4 xr[16];
#pragma unroll
    for (int i = 0; i < 16; i++)
        xr[i] = __ldg(xb + (size_t)t * 4096 + i * 256 + tid);

    CP_WAIT(0);   // own W chunks done; cross-thread visibility via in-loop sync

    // per-lane bases
    const uint32_t a_sm = sbase + SM_XF16
                        + (uint32_t)(32 * warp_r + (l & 15)) * ROWH_B + ((l >> 4) << 4);
    const uint32_t wf_base = sbase + SM_WF + (uint32_t)((warp_c * 8) * 32 + l) * 80;
    const float* sb = (const float*)(smem + SM_B);
    const float* sc = (const float*)(smem + SM_CTX);
    float* pacc = (float*)(smem + SM_PACC);
    char* Hp = smem + SM_XF16;

    for (;;) {
        // ---- convert + store current tile's x (from regs) into shared f16 ----
#pragma unroll
        for (int i = 0; i < 16; i++) {
            int c = i * 256 + tid;
            int row = c >> 5, u = c & 31;
            uint2 p;
            p.x = f16x2_pack(xr[i].x, xr[i].y);
            p.y = f16x2_pack(xr[i].z, xr[i].w);
            *(uint2*)(Hp + row * ROWH_B + u * 8) = p;
        }
        if (tid == 0) smt[0] = (int)atomicAdd(&g_tilectr, 1u);
        __syncthreads();                       // STS visible; smt visible; W visible (1st iter)
        int tn = smt[0];
        bool pend = (tn < NTILES);
        if (pend) {                            // prefetch next tile; hidden under MMA loop
#pragma unroll
            for (int i = 0; i < 16; i++)
                xr[i] = __ldg(xb + (size_t)tn * 4096 + i * 256 + tid);
        }

        float d[2][8][4];
#pragma unroll
        for (int mb = 0; mb < 2; mb++)
#pragma unroll
            for (int nb = 0; nb < 8; nb++)
#pragma unroll
                for (int r = 0; r < 4; r++) d[mb][nb][r] = 0.0f;

#pragma unroll
        for (int st = 0; st < 8; st++) {       // 8 k16 steps (32B each along row)
            uint32_t A[2][4];
            LDSM_X4(A[0][0], A[0][1], A[0][2], A[0][3], a_sm + st * 32);
            LDSM_X4(A[1][0], A[1][1], A[1][2], A[1][3], a_sm + st * 32 + 16 * ROWH_B);
            uint32_t Bv[4][4];
            uint32_t ba = wf_base + (uint32_t)(st * 32) * 80;
#pragma unroll
            for (int q = 0; q < 4; q++)
                LDS128(Bv[q][0], Bv[q][1], Bv[q][2], Bv[q][3], ba + q * 16);
#pragma unroll
            for (int nb = 0; nb < 8; nb++) {
                uint32_t bb0 = Bv[nb >> 1][(nb & 1) * 2];
                uint32_t bb1 = Bv[nb >> 1][(nb & 1) * 2 + 1];
                MMA_F16(d[0][nb], A[0][0], A[0][1], A[0][2], A[0][3], bb0, bb1);
                MMA_F16(d[1][nb], A[1][0], A[1][1], A[1][2], A[1][3], bb0, bb1);
            }
        }

        // ---- epilogue: tanh.approx + ctx-dot on fragments ----
        float acc[4] = {0.f, 0.f, 0.f, 0.f};   // [mb*2 + hi8]
#pragma unroll
        for (int mb = 0; mb < 2; mb++) {
#pragma unroll
            for (int nb = 0; nb < 8; nb++) {
                int cb = 64 * warp_c + nb * 8 + c0 * 2;
#pragma unroll
                for (int r = 0; r < 4; r++) {
                    int c = cb + (r & 1);
                    float th = tanh_approx(d[mb][nb][r] + sb[c]);
                    acc[mb * 2 + (r >> 1)] = fmaf(sc[c], th, acc[mb * 2 + (r >> 1)]);
                }
            }
        }
#pragma unroll
        for (int s = 0; s < 4; s++) {
            acc[s] += __shfl_xor_sync(0xFFFFFFFFu, acc[s], 1);
            acc[s] += __shfl_xor_sync(0xFFFFFFFFu, acc[s], 2);
        }
        if (c0 == 0) {
#pragma unroll
            for (int s = 0; s < 4; s++) {
                int row = 32 * warp_r + 16 * (s >> 1) + 8 * (s & 1) + r0;
                pacc[row * 2 + warp_c] = acc[s];
            }
        }
        __syncthreads();   // pacc ready; also: all Xf16 reads done before next STS

        if (tid < 128) {
            float impv = (pacc[tid * 2] + pacc[tid * 2 + 1]) * 0.08838834764831843f;
            int row = t * 128 + tid;
            float e = 0.0f;
            if (mask[row] != 0) {
                e = __expf(impv);              // |impv| <= ~9: no overflow possible
                int seg = index[row];
                int bq = row / NSEQ;
                atomicAdd(&g_segsum[bq * NIDX + seg], e);
            }
            g_imp[row] = e;
        }

        if (!pend) break;
        t = tn;
    }
}

// ============ K3: weights + scatter-add of x (32 rows/warp, 4-way unrolled) ============
__global__ __launch_bounds__(256)
void k3_scatter(const float* __restrict__ x, const int* __restrict__ index,
                float* __restrict__ out) {
    int warp = (blockIdx.x << 3) + (threadIdx.x >> 5);   // 25000 warps
    int lane = threadIdx.x & 31;
    int rbase = warp * 32;                               // NSEQ % 32 == 0: no bq straddle
    int row = rbase + lane;

    float e  = g_imp[row];
    int seg  = index[row];
    int bq   = row / NSEQ;
    int segg = bq * NIDX + seg;
    float s  = g_segsum[segg];
    float w  = (e != 0.0f) ? e / s : 0.0f;
    out[ATTN_OFF + row] = w;

    const float4* xb = (const float4*)x;
    unsigned act = __ballot_sync(0xFFFFFFFFu, w != 0.0f);
    while (act) {
        int i0 = __ffs(act) - 1;             act &= (act - 1);
        int i1 = act ? __ffs(act) - 1 : -1;  if (i1 >= 0) act &= (act - 1);
        int i2 = act ? __ffs(act) - 1 : -1;  if (i2 >= 0) act &= (act - 1);
        int i3 = act ? __ffs(act) - 1 : -1;  if (i3 >= 0) act &= (act - 1);
        int j1 = i1 < 0 ? 0 : i1, j2 = i2 < 0 ? 0 : i2, j3 = i3 < 0 ? 0 : i3;
        float w0 = __shfl_sync(0xFFFFFFFFu, w, i0);
        float w1 = __shfl_sync(0xFFFFFFFFu, w, j1);
        float w2 = __shfl_sync(0xFFFFFFFFu, w, j2);
        float w3 = __shfl_sync(0xFFFFFFFFu, w, j3);
        int   s0 = __shfl_sync(0xFFFFFFFFu, segg, i0);
        int   s1 = __shfl_sync(0xFFFFFFFFu, segg, j1);
        int   s2 = __shfl_sync(0xFFFFFFFFu, segg, j2);
        int   s3 = __shfl_sync(0xFFFFFFFFu, segg, j3);
        float4 v0 = __ldg(xb + (size_t)(rbase + i0) * 32 + lane);
        float4 v1, v2, v3;
        if (i1 >= 0) v1 = __ldg(xb + (size_t)(rbase + i1) * 32 + lane);
        if (i2 >= 0) v2 = __ldg(xb + (size_t)(rbase + i2) * 32 + lane);
        if (i3 >= 0) v3 = __ldg(xb + (size_t)(rbase + i3) * 32 + lane);
        float* d0 = out + ((size_t)s0 << 7) + lane * 4;
        asm volatile("red.global.add.v4.f32 [%0], {%1, %2, %3, %4};"
                     :: "l"(d0), "f"(v0.x * w0), "f"(v0.y * w0), "f"(v0.z * w0), "f"(v0.w * w0)
                     : "memory");
        if (i1 >= 0) {
            float* d1 = out + ((size_t)s1 << 7) + lane * 4;
            asm volatile("red.global.add.v4.f32 [%0], {%1, %2, %3, %4};"
                         :: "l"(d1), "f"(v1.x * w1), "f"(v1.y * w1), "f"(v1.z * w1), "f"(v1.w * w1)
                         : "memory");
        }
        if (i2 >= 0) {
            float* d2 = out + ((size_t)s2 << 7) + lane * 4;
            asm volatile("red.global.add.v4.f32 [%0], {%1, %2, %3, %4};"
                         :: "l"(d2), "f"(v2.x * w2), "f"(v2.y * w2), "f"(v2.z * w2), "f"(v2.w * w2)
                         : "memory");
        }
        if (i3 >= 0) {
            float* d3 = out + ((size_t)s3 << 7) + lane * 4;
            asm volatile("red.global.add.v4.f32 [%0], {%1, %2, %3, %4};"
                         :: "l"(d3), "f"(v3.x * w3), "f"(v3.y * w3), "f"(v3.z * w3), "f"(v3.w * w3)
                         : "memory");
        }
    }
}

// ============================ launch ============================
extern "C" void kernel_launch(void* const* d_in, const int* in_sizes, int n_in,
                              void* d_out, int out_size) {
    const float* x     = (const float*)d_in[0];
    const float* W     = (const float*)d_in[1];
    const float* bv    = (const float*)d_in[2];
    const float* ctx   = (const float*)d_in[3];
    const int*   mask  = (const int*)d_in[4];
    const int*   index = (const int*)d_in[5];
    float* out = (float*)d_out;

    cudaFuncSetAttribute(k1_importance, cudaFuncAttributeMaxDynamicSharedMemorySize, SMEM_TOTAL);

    k0_init<<<(OUT_ELEMS + 255) / 256, 256>>>(out, W);
    k1_importance<<<152, 256, SMEM_TOTAL>>>(x, bv, ctx, mask, index);
    k3_scatter<<<(ROWS / 256), 256>>>(x, index, out);
}